// round 1
// baseline (speedup 1.0000x reference)
#include <cuda_runtime.h>
#include <math.h>

#define SEQ   2048
#define NH    16
#define DH    64
#define DM    1024
#define BATCH 2
#define MROWS (BATCH*SEQ)   // 4096

// ---------------- scratch (device globals; no allocations allowed) ----------
__device__ float g_q[BATCH*NH*SEQ*DH];      // [b,h,s,d]
__device__ float g_k[BATCH*NH*SEQ*DH];
__device__ float g_v[BATCH*NH*SEQ*DH];
__device__ float g_attn[BATCH*SEQ*DM];      // [b,s,h*64+d]
__device__ float g_bias[NH*4096];           // per-head bias vs (j-i)+2048

// ---------------- relative-position bias table ------------------------------
__global__ void bias_kernel(const float* __restrict__ rel_bias) {
    int h = blockIdx.x;
    for (int i = threadIdx.x; i < 4096; i += blockDim.x) {
        int delta = i - 2048;          // j - i
        int rb = (delta > 0) ? 16 : 0;
        int ar = delta < 0 ? -delta : delta;
        int bucket;
        if (ar < 8) {
            bucket = rb + ar;
        } else {
            // matches float32 ref: 8 + int(log(ar/8)/log(16)*8); log2 form is
            // exact at the only integer-valued boundaries (ar = 16,32,64,128)
            int l = 8 + (int)(2.0f * log2f((float)ar * 0.125f));
            bucket = rb + (l > 15 ? 15 : l);
        }
        g_bias[h*4096 + i] = rel_bias[bucket*NH + h];
    }
}

// ---------------- SGEMM: C[4096x1024] = A[4096x1024] * B[1024x1024] ---------
// REMAP==1: write C into [b,h,s,d] layout (for q/k/v); REMAP==0: plain row-major
template<int REMAP>
__global__ __launch_bounds__(256) void sgemm(const float* __restrict__ A,
                                             const float* __restrict__ B,
                                             float* __restrict__ C) {
    __shared__ float As[16][128];
    __shared__ float Bs[16][128];
    const int tid = threadIdx.x;
    const int tx = tid & 15;        // 0..15  -> 8 cols each
    const int ty = tid >> 4;        // 0..15  -> 8 rows each
    const int m0 = blockIdx.y * 128;
    const int n0 = blockIdx.x * 128;

    float acc[8][8];
    #pragma unroll
    for (int r = 0; r < 8; r++)
        #pragma unroll
        for (int c = 0; c < 8; c++) acc[r][c] = 0.0f;

    for (int kt = 0; kt < DM; kt += 16) {
        #pragma unroll
        for (int i = 0; i < 2; i++) {
            int idx = tid * 2 + i;                 // 0..511
            // A tile 128x16 -> As[k][m] (transposed store)
            int row = idx >> 2;
            int kq  = (idx & 3) * 4;
            float4 a = *(const float4*)&A[(size_t)(m0 + row) * DM + kt + kq];
            As[kq+0][row] = a.x; As[kq+1][row] = a.y;
            As[kq+2][row] = a.z; As[kq+3][row] = a.w;
            // B tile 16x128 -> Bs[k][n] (direct)
            int kk = idx >> 5;
            int nq = (idx & 31) * 4;
            *(float4*)&Bs[kk][nq] = *(const float4*)&B[(size_t)(kt + kk) * DM + n0 + nq];
        }
        __syncthreads();
        #pragma unroll
        for (int kk = 0; kk < 16; kk++) {
            float a[8], b[8];
            *(float4*)&a[0] = *(const float4*)&As[kk][ty*8];
            *(float4*)&a[4] = *(const float4*)&As[kk][ty*8 + 4];
            *(float4*)&b[0] = *(const float4*)&Bs[kk][tx*8];
            *(float4*)&b[4] = *(const float4*)&Bs[kk][tx*8 + 4];
            #pragma unroll
            for (int r = 0; r < 8; r++)
                #pragma unroll
                for (int c = 0; c < 8; c++)
                    acc[r][c] = fmaf(a[r], b[c], acc[r][c]);
        }
        __syncthreads();
    }

    #pragma unroll
    for (int r = 0; r < 8; r++) {
        int m = m0 + ty*8 + r;
        #pragma unroll
        for (int cq = 0; cq < 2; cq++) {
            int n = n0 + tx*8 + cq*4;
            float4 v;
            v.x = acc[r][cq*4+0]; v.y = acc[r][cq*4+1];
            v.z = acc[r][cq*4+2]; v.w = acc[r][cq*4+3];
            if (REMAP) {
                int bb = m >> 11, ss = m & 2047;
                int hh = n >> 6,  dd = n & 63;       // 8-col chunk never crosses a head
                *(float4*)&C[((size_t)(bb*NH + hh) * SEQ + ss) * DH + dd] = v;
            } else {
                *(float4*)&C[(size_t)m * DM + n] = v;
            }
        }
    }
}

// ---------------- flash attention (fp32, online softmax) --------------------
// grid: (SEQ/64, BATCH*NH), block 256. smem: Qs/Ks [d][row] pad 68, Vs/Ps [kk][*] pad 68
#define APAD 68
__global__ __launch_bounds__(256) void attn_kernel() {
    extern __shared__ float sm[];
    float* Qs = sm;                 // [64][68]  d-major
    float* Ks = sm + 64*APAD;       // [64][68]  d-major
    float* Vs = sm + 2*64*APAD;     // [64][68]  kk-major
    float* Ps = sm + 3*64*APAD;     // [64][68]  kk-major (P^T)

    const int tid = threadIdx.x;
    const int tx = tid & 15;        // key-col / d-col group
    const int ty = tid >> 4;        // query-row group
    const int bh = blockIdx.y;      // b*16 + h
    const int h  = bh & 15;
    const int q0 = blockIdx.x * 64;

    const float* qb = g_q + (size_t)bh * SEQ * DH;
    const float* kb = g_k + (size_t)bh * SEQ * DH;
    const float* vb = g_v + (size_t)bh * SEQ * DH;
    const float* bt = g_bias + h * 4096;

    // load Q tile transposed: Qs[d][row]
    #pragma unroll
    for (int i = 0; i < 4; i++) {
        int idx = tid + i*256;          // 0..1023
        int row = idx >> 4;
        int dq  = (idx & 15) * 4;
        float4 v = *(const float4*)&qb[(size_t)(q0 + row) * DH + dq];
        Qs[(dq+0)*APAD + row] = v.x; Qs[(dq+1)*APAD + row] = v.y;
        Qs[(dq+2)*APAD + row] = v.z; Qs[(dq+3)*APAD + row] = v.w;
    }

    float acc[4][4];
    #pragma unroll
    for (int r = 0; r < 4; r++)
        #pragma unroll
        for (int c = 0; c < 4; c++) acc[r][c] = 0.0f;
    float mrow[4], lrow[4];
    #pragma unroll
    for (int r = 0; r < 4; r++) { mrow[r] = -INFINITY; lrow[r] = 0.0f; }

    for (int kt = 0; kt < SEQ/64; kt++) {
        const int k0 = kt * 64;
        __syncthreads();   // Q ready (iter 0) / previous phase-2 done
        // load K (transposed) and V (natural)
        #pragma unroll
        for (int i = 0; i < 4; i++) {
            int idx = tid + i*256;
            int row = idx >> 4;
            int dq  = (idx & 15) * 4;
            float4 kv = *(const float4*)&kb[(size_t)(k0 + row) * DH + dq];
            Ks[(dq+0)*APAD + row] = kv.x; Ks[(dq+1)*APAD + row] = kv.y;
            Ks[(dq+2)*APAD + row] = kv.z; Ks[(dq+3)*APAD + row] = kv.w;
            float4 vv = *(const float4*)&vb[(size_t)(k0 + row) * DH + dq];
            *(float4*)&Vs[row*APAD + dq] = vv;
        }
        __syncthreads();

        // phase 1: S = Q K^T (64x64 tile), 4x4 per thread
        float s[4][4];
        #pragma unroll
        for (int r = 0; r < 4; r++)
            #pragma unroll
            for (int c = 0; c < 4; c++) s[r][c] = 0.0f;
        #pragma unroll 8
        for (int d = 0; d < 64; d++) {
            float q[4], k[4];
            *(float4*)q = *(const float4*)&Qs[d*APAD + ty*4];
            *(float4*)k = *(const float4*)&Ks[d*APAD + tx*4];
            #pragma unroll
            for (int r = 0; r < 4; r++)
                #pragma unroll
                for (int c = 0; c < 4; c++)
                    s[r][c] = fmaf(q[r], k[c], s[r][c]);
        }
        // + relative position bias: delta = (k0+tx*4+c) - (q0+ty*4+r)
        const float* bp = bt + 2048 + (k0 + tx*4) - (q0 + ty*4);
        #pragma unroll
        for (int r = 0; r < 4; r++)
            #pragma unroll
            for (int c = 0; c < 4; c++)
                s[r][c] += bp[c - r];

        // online softmax: reductions across the 16 tx lanes (half-warp groups)
        #pragma unroll
        for (int r = 0; r < 4; r++) {
            float pm = fmaxf(fmaxf(s[r][0], s[r][1]), fmaxf(s[r][2], s[r][3]));
            #pragma unroll
            for (int msk = 1; msk <= 8; msk <<= 1)
                pm = fmaxf(pm, __shfl_xor_sync(0xffffffffu, pm, msk));
            float mn = fmaxf(mrow[r], pm);
            float alpha = expf(mrow[r] - mn);
            mrow[r] = mn;
            float ps = 0.0f;
            #pragma unroll
            for (int c = 0; c < 4; c++) {
                s[r][c] = expf(s[r][c] - mn);
                ps += s[r][c];
            }
            #pragma unroll
            for (int msk = 1; msk <= 8; msk <<= 1)
                ps += __shfl_xor_sync(0xffffffffu, ps, msk);
            lrow[r] = lrow[r] * alpha + ps;
            #pragma unroll
            for (int c = 0; c < 4; c++) acc[r][c] *= alpha;
            // store P transposed: Ps[kk][row]
            #pragma unroll
            for (int c = 0; c < 4; c++)
                Ps[(tx*4 + c)*APAD + ty*4 + r] = s[r][c];
        }
        __syncthreads();

        // phase 2: O += P V
        #pragma unroll 8
        for (int kk = 0; kk < 64; kk++) {
            float p[4], v[4];
            *(float4*)p = *(const float4*)&Ps[kk*APAD + ty*4];
            *(float4*)v = *(const float4*)&Vs[kk*APAD + tx*4];
            #pragma unroll
            for (int r = 0; r < 4; r++)
                #pragma unroll
                for (int c = 0; c < 4; c++)
                    acc[r][c] = fmaf(p[r], v[c], acc[r][c]);
        }
    }

    // epilogue: normalize and write to g_attn[b, s, h*64+d]
    const int b = bh >> 4;
    #pragma unroll
    for (int r = 0; r < 4; r++) {
        float inv = 1.0f / lrow[r];
        size_t o = ((size_t)(b*SEQ + q0 + ty*4 + r)) * DM + h*DH + tx*4;
        float4 v;
        v.x = acc[r][0]*inv; v.y = acc[r][1]*inv;
        v.z = acc[r][2]*inv; v.w = acc[r][3]*inv;
        *(float4*)&g_attn[o] = v;
    }
}

// ---------------- launch -----------------------------------------------------
extern "C" void kernel_launch(void* const* d_in, const int* in_sizes, int n_in,
                              void* d_out, int out_size) {
    const float* hidden = (const float*)d_in[0];
    const float* Wq     = (const float*)d_in[1];
    const float* Wk     = (const float*)d_in[2];
    const float* Wv     = (const float*)d_in[3];
    const float* Wo     = (const float*)d_in[4];
    const float* relb   = (const float*)d_in[5];
    float* out = (float*)d_out;

    float *pq, *pk, *pv, *pa;
    cudaGetSymbolAddress((void**)&pq, g_q);
    cudaGetSymbolAddress((void**)&pk, g_k);
    cudaGetSymbolAddress((void**)&pv, g_v);
    cudaGetSymbolAddress((void**)&pa, g_attn);

    bias_kernel<<<NH, 256>>>(relb);

    dim3 gg(DM/128, MROWS/128);
    sgemm<1><<<gg, 256>>>(hidden, Wq, pq);
    sgemm<1><<<gg, 256>>>(hidden, Wk, pk);
    sgemm<1><<<gg, 256>>>(hidden, Wv, pv);

    int smem = 4 * 64 * APAD * (int)sizeof(float);   // 69632
    cudaFuncSetAttribute(attn_kernel, cudaFuncAttributeMaxDynamicSharedMemorySize, smem);
    attn_kernel<<<dim3(SEQ/64, BATCH*NH), 256, smem>>>();

    sgemm<0><<<gg, 256>>>(pa, Wo, out);
}

// round 3
// speedup vs baseline: 1.3010x; 1.3010x over previous
#include <cuda_runtime.h>
#include <cuda_bf16.h>
#include <math.h>
#include <stdint.h>

#define SEQ   2048
#define NH    16
#define DH    64
#define DM    1024
#define BATCH 2
#define MROWS (BATCH*SEQ)   // 4096

// ---------------- scratch (device globals; no allocations allowed) ----------
__device__ float g_q[MROWS*DM];             // [b,s,h*64+d] fp32
__device__ float g_k[MROWS*DM];
__device__ float g_v[MROWS*DM];
__device__ float g_bias[NH*4096];           // per-head bias vs (j-i)+2048
__device__ unsigned short g_hh[MROWS*DM];   // hidden bf16 hi
__device__ unsigned short g_hl[MROWS*DM];   // hidden bf16 lo
__device__ unsigned short g_ah[MROWS*DM];   // attn out bf16 hi
__device__ unsigned short g_al[MROWS*DM];   // attn out bf16 lo
__device__ unsigned short g_wh[4][DM*DM];   // W transposed [n][k] bf16 hi (q,k,v,o)
__device__ unsigned short g_wl[4][DM*DM];   // lo

// ======================= helpers =============================================
__device__ __forceinline__ uint32_t smem_u32(const void* p) {
    uint32_t a;
    asm("{ .reg .u64 t; cvta.to.shared.u64 t, %1; cvt.u32.u64 %0, t; }" : "=r"(a) : "l"(p));
    return a;
}
__device__ __forceinline__ void cp_async16(uint32_t dst, const void* src) {
    asm volatile("cp.async.cg.shared.global [%0], [%1], 16;" :: "r"(dst), "l"(src));
}
#define CP_COMMIT() asm volatile("cp.async.commit_group;" ::: "memory")
#define CP_WAIT(N)  asm volatile("cp.async.wait_group %0;" :: "n"(N) : "memory")

#define LDSM4(r, addr) \
    asm volatile("ldmatrix.sync.aligned.m8n8.x4.shared.b16 {%0,%1,%2,%3}, [%4];" \
        : "=r"((r)[0]), "=r"((r)[1]), "=r"((r)[2]), "=r"((r)[3]) : "r"(addr))

#define MMA16816(c, a, b0, b1) \
    asm volatile("mma.sync.aligned.m16n8k16.row.col.f32.bf16.bf16.f32 " \
        "{%0,%1,%2,%3}, {%4,%5,%6,%7}, {%8,%9}, {%0,%1,%2,%3};" \
        : "+f"((c)[0]), "+f"((c)[1]), "+f"((c)[2]), "+f"((c)[3]) \
        : "r"((a)[0]), "r"((a)[1]), "r"((a)[2]), "r"((a)[3]), "r"(b0), "r"(b1))

// ---------------- relative-position bias table ------------------------------
__global__ void bias_kernel(const float* __restrict__ rel_bias) {
    int h = blockIdx.x;
    for (int i = threadIdx.x; i < 4096; i += blockDim.x) {
        int delta = i - 2048;          // j - i
        int rb = (delta > 0) ? 16 : 0;
        int ar = delta < 0 ? -delta : delta;
        int bucket;
        if (ar < 8) {
            bucket = rb + ar;
        } else {
            int l = 8 + (int)(2.0f * log2f((float)ar * 0.125f));
            bucket = rb + (l > 15 ? 15 : l);
        }
        g_bias[h*4096 + i] = rel_bias[bucket*NH + h];
    }
}

// ---------------- fp32 -> bf16 hi/lo split (elementwise) --------------------
__global__ void convert_split(const float* __restrict__ x,
                              __nv_bfloat16* __restrict__ oh,
                              __nv_bfloat16* __restrict__ ol) {
    int i = blockIdx.x * blockDim.x + threadIdx.x;
    float4 v = ((const float4*)x)[i];
    __nv_bfloat16 h0 = __float2bfloat16_rn(v.x);
    __nv_bfloat16 h1 = __float2bfloat16_rn(v.y);
    __nv_bfloat16 h2 = __float2bfloat16_rn(v.z);
    __nv_bfloat16 h3 = __float2bfloat16_rn(v.w);
    __nv_bfloat16 l0 = __float2bfloat16_rn(v.x - __bfloat162float(h0));
    __nv_bfloat16 l1 = __float2bfloat16_rn(v.y - __bfloat162float(h1));
    __nv_bfloat16 l2 = __float2bfloat16_rn(v.z - __bfloat162float(h2));
    __nv_bfloat16 l3 = __float2bfloat16_rn(v.w - __bfloat162float(h3));
    __nv_bfloat162* ph = (__nv_bfloat162*)(oh + 4*(size_t)i);
    __nv_bfloat162* pl = (__nv_bfloat162*)(ol + 4*(size_t)i);
    ph[0] = __halves2bfloat162(h0, h1);
    ph[1] = __halves2bfloat162(h2, h3);
    pl[0] = __halves2bfloat162(l0, l1);
    pl[1] = __halves2bfloat162(l2, l3);
}

// ---------------- W: fp32 [k][n] -> bf16 hi/lo transposed [n][k] -------------
__global__ void convert_w_t(const float* __restrict__ W,
                            __nv_bfloat16* __restrict__ oh,
                            __nv_bfloat16* __restrict__ ol) {
    __shared__ float t[32][33];
    int tx = threadIdx.x, ty = threadIdx.y;
    int n0 = blockIdx.x * 32, k0 = blockIdx.y * 32;
    #pragma unroll
    for (int j = 0; j < 32; j += 8)
        t[ty + j][tx] = W[(size_t)(k0 + ty + j) * DM + n0 + tx];
    __syncthreads();
    #pragma unroll
    for (int j = 0; j < 32; j += 8) {
        float v = t[tx][ty + j];
        size_t o = (size_t)(n0 + ty + j) * DM + k0 + tx;
        __nv_bfloat16 h = __float2bfloat16_rn(v);
        oh[o] = h;
        ol[o] = __float2bfloat16_rn(v - __bfloat162float(h));
    }
}

// ============== HMMA GEMM: C[4096x1024] = (Ah+Al)(Bh+Bl)^T ==================
// A: [M,K] K-major bf16 hi/lo. B: [N,K] K-major bf16 hi/lo.
// CTA 128M x 256N, 256 threads (8 warps 2Mx4N, warp 64x64), K-chunk 32,
// 3-stage cp.async. grid (4, 32) = 128 CTAs = one wave.
#define KCH     32
#define NCHUNK  (DM/KCH)          // 32
#define PITCHB  80                // bytes per smem row (32 bf16 + 8 pad)
#define SA_H    0
#define SA_L    10240
#define SB_H    20480
#define SB_L    40960
#define STAGEB  61440
#define GEMM_SMEM (3*STAGEB)

__global__ __launch_bounds__(256, 1) void gemm_mma(
    const __nv_bfloat16* __restrict__ Ah, const __nv_bfloat16* __restrict__ Al,
    const __nv_bfloat16* __restrict__ Bh, const __nv_bfloat16* __restrict__ Bl,
    float* __restrict__ C)
{
    extern __shared__ char smem[];
    const uint32_t sb0 = smem_u32(smem);
    const int tid  = threadIdx.x;
    const int wid  = tid >> 5;
    const int lane = tid & 31;
    const int wm   = wid >> 2;          // 0..1  (M warp)
    const int wn   = wid & 3;           // 0..3  (N warp)
    const int m0 = blockIdx.y * 128;
    const int n0 = blockIdx.x * 256;

    // per-lane ldmatrix row/col-half offset (within a 16-row tile)
    const uint32_t lrow  = lane & 15;
    const uint32_t lhalf = (lane >> 4) & 1;
    const uint32_t loff  = lrow * PITCHB + lhalf * 16;

    float c[4][8][4];
    #pragma unroll
    for (int mt = 0; mt < 4; mt++)
        #pragma unroll
        for (int nt = 0; nt < 8; nt++)
            #pragma unroll
            for (int q = 0; q < 4; q++) c[mt][nt][q] = 0.0f;

    #define LOAD_CHUNK(j) do { \
        const uint32_t sb = sb0 + ((j) % 3) * STAGEB; \
        const int k0 = (j) * KCH; \
        _Pragma("unroll") \
        for (int t = 0; t < 2; t++) { \
            int idx = tid + t*256; int r = idx >> 2, cc = idx & 3; \
            cp_async16(sb + SA_H + r*PITCHB + cc*16, Ah + (size_t)(m0+r)*DM + k0 + cc*8); \
            cp_async16(sb + SA_L + r*PITCHB + cc*16, Al + (size_t)(m0+r)*DM + k0 + cc*8); \
        } \
        _Pragma("unroll") \
        for (int t = 0; t < 4; t++) { \
            int idx = tid + t*256; int r = idx >> 2, cc = idx & 3; \
            cp_async16(sb + SB_H + r*PITCHB + cc*16, Bh + (size_t)(n0+r)*DM + k0 + cc*8); \
            cp_async16(sb + SB_L + r*PITCHB + cc*16, Bl + (size_t)(n0+r)*DM + k0 + cc*8); \
        } \
        CP_COMMIT(); \
    } while (0)

    LOAD_CHUNK(0);
    LOAD_CHUNK(1);

    #pragma unroll 1
    for (int i = 0; i < NCHUNK; i++) {
        if (i < NCHUNK - 1) { CP_WAIT(1); } else { CP_WAIT(0); }
        __syncthreads();
        if (i + 2 < NCHUNK) LOAD_CHUNK(i + 2);

        const uint32_t sb = sb0 + (i % 3) * STAGEB;
        #pragma unroll
        for (int kk = 0; kk < 2; kk++) {
            const uint32_t koff = kk * 32;    // 16 bf16 = 32 bytes
            uint32_t a[4][4], a2[4][4], b[4][4];
            // A hi + B hi
            #pragma unroll
            for (int mt = 0; mt < 4; mt++)
                LDSM4(a[mt], sb + SA_H + (wm*64 + mt*16)*PITCHB + loff + koff);
            #pragma unroll
            for (int p = 0; p < 4; p++)
                LDSM4(b[p], sb + SB_H + (wn*64 + p*16)*PITCHB + loff + koff);
            #pragma unroll
            for (int mt = 0; mt < 4; mt++)
                #pragma unroll
                for (int p = 0; p < 4; p++) {
                    MMA16816(c[mt][2*p],   a[mt], b[p][0], b[p][2]);
                    MMA16816(c[mt][2*p+1], a[mt], b[p][1], b[p][3]);
                }
            // A lo x B hi
            #pragma unroll
            for (int mt = 0; mt < 4; mt++)
                LDSM4(a2[mt], sb + SA_L + (wm*64 + mt*16)*PITCHB + loff + koff);
            #pragma unroll
            for (int mt = 0; mt < 4; mt++)
                #pragma unroll
                for (int p = 0; p < 4; p++) {
                    MMA16816(c[mt][2*p],   a2[mt], b[p][0], b[p][2]);
                    MMA16816(c[mt][2*p+1], a2[mt], b[p][1], b[p][3]);
                }
            // A hi x B lo (reuse b regs)
            #pragma unroll
            for (int p = 0; p < 4; p++)
                LDSM4(b[p], sb + SB_L + (wn*64 + p*16)*PITCHB + loff + koff);
            #pragma unroll
            for (int mt = 0; mt < 4; mt++)
                #pragma unroll
                for (int p = 0; p < 4; p++) {
                    MMA16816(c[mt][2*p],   a[mt], b[p][0], b[p][2]);
                    MMA16816(c[mt][2*p+1], a[mt], b[p][1], b[p][3]);
                }
        }
    }
    #undef LOAD_CHUNK

    // epilogue: write fp32 C
    const int rbase = m0 + wm*64 + (lane >> 2);
    const int cbase = n0 + wn*64 + (lane & 3) * 2;
    #pragma unroll
    for (int mt = 0; mt < 4; mt++) {
        #pragma unroll
        for (int nt = 0; nt < 8; nt++) {
            int row = rbase + mt*16;
            int col = cbase + nt*8;
            float2 v0; v0.x = c[mt][nt][0]; v0.y = c[mt][nt][1];
            float2 v1; v1.x = c[mt][nt][2]; v1.y = c[mt][nt][3];
            *(float2*)&C[(size_t)row * DM + col]       = v0;
            *(float2*)&C[(size_t)(row + 8) * DM + col] = v1;
        }
    }
}

// ---------------- flash attention (fp32, online softmax) --------------------
// q/k/v in [b, s, h*64+d] layout. Output written as bf16 hi/lo for Wo GEMM.
#define APAD 68
__global__ __launch_bounds__(256) void attn_kernel() {
    extern __shared__ float sm[];
    float* Qs = sm;                 // [64][68]  d-major
    float* Ks = sm + 64*APAD;       // [64][68]  d-major
    float* Vs = sm + 2*64*APAD;     // [64][68]  kk-major
    float* Ps = sm + 3*64*APAD;     // [64][68]  kk-major (P^T)

    const int tid = threadIdx.x;
    const int tx = tid & 15;
    const int ty = tid >> 4;
    const int bh = blockIdx.y;      // b*16 + h
    const int h  = bh & 15;
    const int b  = bh >> 4;
    const int q0 = blockIdx.x * 64;

    const float* qb = g_q + (size_t)b * SEQ * DM + h * DH;
    const float* kb = g_k + (size_t)b * SEQ * DM + h * DH;
    const float* vb = g_v + (size_t)b * SEQ * DM + h * DH;
    const float* bt = g_bias + h * 4096;

    #pragma unroll
    for (int i = 0; i < 4; i++) {
        int idx = tid + i*256;
        int row = idx >> 4;
        int dq  = (idx & 15) * 4;
        float4 v = *(const float4*)&qb[(size_t)(q0 + row) * DM + dq];
        Qs[(dq+0)*APAD + row] = v.x; Qs[(dq+1)*APAD + row] = v.y;
        Qs[(dq+2)*APAD + row] = v.z; Qs[(dq+3)*APAD + row] = v.w;
    }

    float acc[4][4];
    #pragma unroll
    for (int r = 0; r < 4; r++)
        #pragma unroll
        for (int c = 0; c < 4; c++) acc[r][c] = 0.0f;
    float mrow[4], lrow[4];
    #pragma unroll
    for (int r = 0; r < 4; r++) { mrow[r] = -INFINITY; lrow[r] = 0.0f; }

    for (int kt = 0; kt < SEQ/64; kt++) {
        const int k0 = kt * 64;
        __syncthreads();
        #pragma unroll
        for (int i = 0; i < 4; i++) {
            int idx = tid + i*256;
            int row = idx >> 4;
            int dq  = (idx & 15) * 4;
            float4 kv = *(const float4*)&kb[(size_t)(k0 + row) * DM + dq];
            Ks[(dq+0)*APAD + row] = kv.x; Ks[(dq+1)*APAD + row] = kv.y;
            Ks[(dq+2)*APAD + row] = kv.z; Ks[(dq+3)*APAD + row] = kv.w;
            float4 vv = *(const float4*)&vb[(size_t)(k0 + row) * DM + dq];
            *(float4*)&Vs[row*APAD + dq] = vv;
        }
        __syncthreads();

        float s[4][4];
        #pragma unroll
        for (int r = 0; r < 4; r++)
            #pragma unroll
            for (int c = 0; c < 4; c++) s[r][c] = 0.0f;
        #pragma unroll 8
        for (int d = 0; d < 64; d++) {
            float q[4], k[4];
            *(float4*)q = *(const float4*)&Qs[d*APAD + ty*4];
            *(float4*)k = *(const float4*)&Ks[d*APAD + tx*4];
            #pragma unroll
            for (int r = 0; r < 4; r++)
                #pragma unroll
                for (int c = 0; c < 4; c++)
                    s[r][c] = fmaf(q[r], k[c], s[r][c]);
        }
        const float* bp = bt + 2048 + (k0 + tx*4) - (q0 + ty*4);
        #pragma unroll
        for (int r = 0; r < 4; r++)
            #pragma unroll
            for (int c = 0; c < 4; c++)
                s[r][c] += bp[c - r];

        #pragma unroll
        for (int r = 0; r < 4; r++) {
            float pm = fmaxf(fmaxf(s[r][0], s[r][1]), fmaxf(s[r][2], s[r][3]));
            #pragma unroll
            for (int msk = 1; msk <= 8; msk <<= 1)
                pm = fmaxf(pm, __shfl_xor_sync(0xffffffffu, pm, msk));
            float mn = fmaxf(mrow[r], pm);
            float alpha = expf(mrow[r] - mn);
            mrow[r] = mn;
            float ps = 0.0f;
            #pragma unroll
            for (int c = 0; c < 4; c++) {
                s[r][c] = expf(s[r][c] - mn);
                ps += s[r][c];
            }
            #pragma unroll
            for (int msk = 1; msk <= 8; msk <<= 1)
                ps += __shfl_xor_sync(0xffffffffu, ps, msk);
            lrow[r] = lrow[r] * alpha + ps;
            #pragma unroll
            for (int c = 0; c < 4; c++) acc[r][c] *= alpha;
            #pragma unroll
            for (int c = 0; c < 4; c++)
                Ps[(tx*4 + c)*APAD + ty*4 + r] = s[r][c];
        }
        __syncthreads();

        #pragma unroll 8
        for (int kk = 0; kk < 64; kk++) {
            float p[4], v[4];
            *(float4*)p = *(const float4*)&Ps[kk*APAD + ty*4];
            *(float4*)v = *(const float4*)&Vs[kk*APAD + tx*4];
            #pragma unroll
            for (int r = 0; r < 4; r++)
                #pragma unroll
                for (int c = 0; c < 4; c++)
                    acc[r][c] = fmaf(p[r], v[c], acc[r][c]);
        }
    }

    // epilogue: normalize, split to bf16 hi/lo for Wo GEMM
    __nv_bfloat16* oh = (__nv_bfloat16*)g_ah;
    __nv_bfloat16* ol = (__nv_bfloat16*)g_al;
    #pragma unroll
    for (int r = 0; r < 4; r++) {
        float inv = 1.0f / lrow[r];
        size_t o = ((size_t)(b*SEQ + q0 + ty*4 + r)) * DM + h*DH + tx*4;
        float v0 = acc[r][0]*inv, v1 = acc[r][1]*inv, v2 = acc[r][2]*inv, v3 = acc[r][3]*inv;
        __nv_bfloat16 h0 = __float2bfloat16_rn(v0), h1 = __float2bfloat16_rn(v1);
        __nv_bfloat16 h2 = __float2bfloat16_rn(v2), h3 = __float2bfloat16_rn(v3);
        *(__nv_bfloat162*)&oh[o]   = __halves2bfloat162(h0, h1);
        *(__nv_bfloat162*)&oh[o+2] = __halves2bfloat162(h2, h3);
        __nv_bfloat16 l0 = __float2bfloat16_rn(v0 - __bfloat162float(h0));
        __nv_bfloat16 l1 = __float2bfloat16_rn(v1 - __bfloat162float(h1));
        __nv_bfloat16 l2 = __float2bfloat16_rn(v2 - __bfloat162float(h2));
        __nv_bfloat16 l3 = __float2bfloat16_rn(v3 - __bfloat162float(h3));
        *(__nv_bfloat162*)&ol[o]   = __halves2bfloat162(l0, l1);
        *(__nv_bfloat162*)&ol[o+2] = __halves2bfloat162(l2, l3);
    }
}

// ---------------- launch -----------------------------------------------------
extern "C" void kernel_launch(void* const* d_in, const int* in_sizes, int n_in,
                              void* d_out, int out_size) {
    const float* hidden = (const float*)d_in[0];
    const float* Wq     = (const float*)d_in[1];
    const float* Wk     = (const float*)d_in[2];
    const float* Wv     = (const float*)d_in[3];
    const float* Wo     = (const float*)d_in[4];
    const float* relb   = (const float*)d_in[5];
    float* out = (float*)d_out;

    float *pq, *pk, *pv;
    void *phh, *phl, *pah, *pal, *pwh, *pwl;
    cudaGetSymbolAddress((void**)&pq, g_q);
    cudaGetSymbolAddress((void**)&pk, g_k);
    cudaGetSymbolAddress((void**)&pv, g_v);
    cudaGetSymbolAddress(&phh, g_hh);
    cudaGetSymbolAddress(&phl, g_hl);
    cudaGetSymbolAddress(&pah, g_ah);
    cudaGetSymbolAddress(&pal, g_al);
    cudaGetSymbolAddress(&pwh, g_wh);
    cudaGetSymbolAddress(&pwl, g_wl);

    __nv_bfloat16* hh = (__nv_bfloat16*)phh;
    __nv_bfloat16* hl = (__nv_bfloat16*)phl;
    __nv_bfloat16* ah = (__nv_bfloat16*)pah;
    __nv_bfloat16* al = (__nv_bfloat16*)pal;
    __nv_bfloat16* wh = (__nv_bfloat16*)pwh;   // [4][DM*DM]
    __nv_bfloat16* wl = (__nv_bfloat16*)pwl;

    convert_split<<<(MROWS*DM/4)/256, 256>>>(hidden, hh, hl);
    dim3 tg(DM/32, DM/32), tb(32, 8);
    convert_w_t<<<tg, tb>>>(Wq, wh + 0*DM*DM, wl + 0*DM*DM);
    convert_w_t<<<tg, tb>>>(Wk, wh + 1*DM*DM, wl + 1*DM*DM);
    convert_w_t<<<tg, tb>>>(Wv, wh + 2*DM*DM, wl + 2*DM*DM);
    convert_w_t<<<tg, tb>>>(Wo, wh + 3*DM*DM, wl + 3*DM*DM);
    bias_kernel<<<NH, 256>>>(relb);

    cudaFuncSetAttribute(gemm_mma, cudaFuncAttributeMaxDynamicSharedMemorySize, GEMM_SMEM);
    dim3 gg(DM/256, MROWS/128);   // (4, 32)
    gemm_mma<<<gg, 256, GEMM_SMEM>>>(hh, hl, wh + 0*DM*DM, wl + 0*DM*DM, pq);
    gemm_mma<<<gg, 256, GEMM_SMEM>>>(hh, hl, wh + 1*DM*DM, wl + 1*DM*DM, pk);
    gemm_mma<<<gg, 256, GEMM_SMEM>>>(hh, hl, wh + 2*DM*DM, wl + 2*DM*DM, pv);

    int smem = 4 * 64 * APAD * (int)sizeof(float);   // 69632
    cudaFuncSetAttribute(attn_kernel, cudaFuncAttributeMaxDynamicSharedMemorySize, smem);
    attn_kernel<<<dim3(SEQ/64, BATCH*NH), 256, smem>>>();

    gemm_mma<<<gg, 256, GEMM_SMEM>>>(ah, al, wh + 3*DM*DM, wl + 3*DM*DM, out);
}

// round 4
// speedup vs baseline: 2.4528x; 1.8853x over previous
#include <cuda_runtime.h>
#include <cuda_bf16.h>
#include <math.h>
#include <stdint.h>

#define SEQ   2048
#define NH    16
#define DH    64
#define DM    1024
#define BATCH 2
#define MROWS (BATCH*SEQ)   // 4096

// ---------------- scratch (device globals; no allocations allowed) ----------
__device__ float g_bias[NH*4096];           // per-head bias vs (j-i)+2048
__device__ unsigned short g_hh[MROWS*DM];   // hidden bf16 hi
__device__ unsigned short g_hl[MROWS*DM];   // hidden bf16 lo
__device__ unsigned short g_qh[MROWS*DM];   // q bf16 hi  [b,s,h*64+d]
__device__ unsigned short g_ql[MROWS*DM];
__device__ unsigned short g_kh[MROWS*DM];
__device__ unsigned short g_kl[MROWS*DM];
__device__ unsigned short g_vh[MROWS*DM];
__device__ unsigned short g_vl[MROWS*DM];
__device__ unsigned short g_ah[MROWS*DM];   // attn out bf16 hi
__device__ unsigned short g_al[MROWS*DM];
__device__ unsigned short g_wh[4][DM*DM];   // W transposed [n][k] bf16 hi (q,k,v,o)
__device__ unsigned short g_wl[4][DM*DM];

// ======================= helpers =============================================
__device__ __forceinline__ uint32_t smem_u32(const void* p) {
    uint32_t a;
    asm("{ .reg .u64 t; cvta.to.shared.u64 t, %1; cvt.u32.u64 %0, t; }" : "=r"(a) : "l"(p));
    return a;
}
__device__ __forceinline__ void cp_async16(uint32_t dst, const void* src) {
    asm volatile("cp.async.cg.shared.global [%0], [%1], 16;" :: "r"(dst), "l"(src));
}
#define CP_COMMIT() asm volatile("cp.async.commit_group;" ::: "memory")
#define CP_WAIT(N)  asm volatile("cp.async.wait_group %0;" :: "n"(N) : "memory")

#define LDSM4(r, addr) \
    asm volatile("ldmatrix.sync.aligned.m8n8.x4.shared.b16 {%0,%1,%2,%3}, [%4];" \
        : "=r"((r)[0]), "=r"((r)[1]), "=r"((r)[2]), "=r"((r)[3]) : "r"(addr))
#define LDSM4T(r, addr) \
    asm volatile("ldmatrix.sync.aligned.m8n8.x4.trans.shared.b16 {%0,%1,%2,%3}, [%4];" \
        : "=r"((r)[0]), "=r"((r)[1]), "=r"((r)[2]), "=r"((r)[3]) : "r"(addr))

#define MMA16816(c, a, b0, b1) \
    asm volatile("mma.sync.aligned.m16n8k16.row.col.f32.bf16.bf16.f32 " \
        "{%0,%1,%2,%3}, {%4,%5,%6,%7}, {%8,%9}, {%0,%1,%2,%3};" \
        : "+f"((c)[0]), "+f"((c)[1]), "+f"((c)[2]), "+f"((c)[3]) \
        : "r"((a)[0]), "r"((a)[1]), "r"((a)[2]), "r"((a)[3]), "r"(b0), "r"(b1))

__device__ __forceinline__ uint32_t pack_bf2(float x, float y) {
    __nv_bfloat162 t = __floats2bfloat162_rn(x, y);
    return *(uint32_t*)&t;
}
__device__ __forceinline__ float2 unpack_bf2(uint32_t u) {
    __nv_bfloat162 t = *(__nv_bfloat162*)&u;
    return __bfloat1622float2(t);
}

// fast exp on the FMA pipe (args <= 0; clamp keeps scale exponent valid)
__device__ __forceinline__ float expp(float x) {
    x = fmaxf(x, -80.0f);
    float y = x * 1.4426950408889634f;
    float t = y + 12582912.0f;              // round-to-nearest int
    int   n = __float_as_int(t) - 0x4B400000;
    float f = y - (t - 12582912.0f);        // frac in [-0.5, 0.5]
    float g = f * 0.6931471805599453f;
    float p = fmaf(g, 0.008333333f, 0.041666668f);
    p = fmaf(p, g, 0.16666667f);
    p = fmaf(p, g, 0.5f);
    p = fmaf(p, g, 1.0f);
    p = fmaf(p, g, 1.0f);
    return p * __int_as_float((n + 127) << 23);
}

// ---------------- relative-position bias table ------------------------------
__global__ void bias_kernel(const float* __restrict__ rel_bias) {
    int h = blockIdx.x;
    for (int i = threadIdx.x; i < 4096; i += blockDim.x) {
        int delta = i - 2048;          // j - i
        int rb = (delta > 0) ? 16 : 0;
        int ar = delta < 0 ? -delta : delta;
        int bucket;
        if (ar < 8) {
            bucket = rb + ar;
        } else {
            int l = 8 + (int)(2.0f * log2f((float)ar * 0.125f));
            bucket = rb + (l > 15 ? 15 : l);
        }
        g_bias[h*4096 + i] = rel_bias[bucket*NH + h];
    }
}

// ---------------- fp32 -> bf16 hi/lo split (elementwise) --------------------
__global__ void convert_split(const float* __restrict__ x,
                              __nv_bfloat16* __restrict__ oh,
                              __nv_bfloat16* __restrict__ ol) {
    int i = blockIdx.x * blockDim.x + threadIdx.x;
    float4 v = ((const float4*)x)[i];
    __nv_bfloat16 h0 = __float2bfloat16_rn(v.x);
    __nv_bfloat16 h1 = __float2bfloat16_rn(v.y);
    __nv_bfloat16 h2 = __float2bfloat16_rn(v.z);
    __nv_bfloat16 h3 = __float2bfloat16_rn(v.w);
    __nv_bfloat16 l0 = __float2bfloat16_rn(v.x - __bfloat162float(h0));
    __nv_bfloat16 l1 = __float2bfloat16_rn(v.y - __bfloat162float(h1));
    __nv_bfloat16 l2 = __float2bfloat16_rn(v.z - __bfloat162float(h2));
    __nv_bfloat16 l3 = __float2bfloat16_rn(v.w - __bfloat162float(h3));
    __nv_bfloat162* ph = (__nv_bfloat162*)(oh + 4*(size_t)i);
    __nv_bfloat162* pl = (__nv_bfloat162*)(ol + 4*(size_t)i);
    ph[0] = __halves2bfloat162(h0, h1);
    ph[1] = __halves2bfloat162(h2, h3);
    pl[0] = __halves2bfloat162(l0, l1);
    pl[1] = __halves2bfloat162(l2, l3);
}

// ---------------- W: fp32 [k][n] -> bf16 hi/lo transposed [n][k] -------------
__global__ void convert_w_t(const float* __restrict__ W,
                            __nv_bfloat16* __restrict__ oh,
                            __nv_bfloat16* __restrict__ ol) {
    __shared__ float t[32][33];
    int tx = threadIdx.x, ty = threadIdx.y;
    int n0 = blockIdx.x * 32, k0 = blockIdx.y * 32;
    #pragma unroll
    for (int j = 0; j < 32; j += 8)
        t[ty + j][tx] = W[(size_t)(k0 + ty + j) * DM + n0 + tx];
    __syncthreads();
    #pragma unroll
    for (int j = 0; j < 32; j += 8) {
        float v = t[tx][ty + j];
        size_t o = (size_t)(n0 + ty + j) * DM + k0 + tx;
        __nv_bfloat16 h = __float2bfloat16_rn(v);
        oh[o] = h;
        ol[o] = __float2bfloat16_rn(v - __bfloat162float(h));
    }
}

// ============== HMMA GEMM: C[4096x1024] = (Ah+Al)(Bh+Bl)^T ==================
// SPLIT=1: write bf16 hi/lo (Ch/Cl); SPLIT=0: write fp32 C.
#define KCH     32
#define NCHUNK  (DM/KCH)          // 32
#define PITCHB  80
#define SA_H    0
#define SA_L    10240
#define SB_H    20480
#define SB_L    40960
#define STAGEB  61440
#define GEMM_SMEM (3*STAGEB)

template<int SPLIT>
__global__ __launch_bounds__(256, 1) void gemm_mma(
    const __nv_bfloat16* __restrict__ Ah, const __nv_bfloat16* __restrict__ Al,
    const __nv_bfloat16* __restrict__ Bh, const __nv_bfloat16* __restrict__ Bl,
    float* __restrict__ C,
    __nv_bfloat16* __restrict__ Ch, __nv_bfloat16* __restrict__ Cl)
{
    extern __shared__ char smem[];
    const uint32_t sb0 = smem_u32(smem);
    const int tid  = threadIdx.x;
    const int wid  = tid >> 5;
    const int lane = tid & 31;
    const int wm   = wid >> 2;
    const int wn   = wid & 3;
    const int m0 = blockIdx.y * 128;
    const int n0 = blockIdx.x * 256;

    const uint32_t lrow  = lane & 15;
    const uint32_t lhalf = (lane >> 4) & 1;
    const uint32_t loff  = lrow * PITCHB + lhalf * 16;

    float c[4][8][4];
    #pragma unroll
    for (int mt = 0; mt < 4; mt++)
        #pragma unroll
        for (int nt = 0; nt < 8; nt++)
            #pragma unroll
            for (int q = 0; q < 4; q++) c[mt][nt][q] = 0.0f;

    #define LOAD_CHUNK(j) do { \
        const uint32_t sb = sb0 + ((j) % 3) * STAGEB; \
        const int k0 = (j) * KCH; \
        _Pragma("unroll") \
        for (int t = 0; t < 2; t++) { \
            int idx = tid + t*256; int r = idx >> 2, cc = idx & 3; \
            cp_async16(sb + SA_H + r*PITCHB + cc*16, Ah + (size_t)(m0+r)*DM + k0 + cc*8); \
            cp_async16(sb + SA_L + r*PITCHB + cc*16, Al + (size_t)(m0+r)*DM + k0 + cc*8); \
        } \
        _Pragma("unroll") \
        for (int t = 0; t < 4; t++) { \
            int idx = tid + t*256; int r = idx >> 2, cc = idx & 3; \
            cp_async16(sb + SB_H + r*PITCHB + cc*16, Bh + (size_t)(n0+r)*DM + k0 + cc*8); \
            cp_async16(sb + SB_L + r*PITCHB + cc*16, Bl + (size_t)(n0+r)*DM + k0 + cc*8); \
        } \
        CP_COMMIT(); \
    } while (0)

    LOAD_CHUNK(0);
    LOAD_CHUNK(1);

    #pragma unroll 1
    for (int i = 0; i < NCHUNK; i++) {
        if (i < NCHUNK - 1) { CP_WAIT(1); } else { CP_WAIT(0); }
        __syncthreads();
        if (i + 2 < NCHUNK) LOAD_CHUNK(i + 2);

        const uint32_t sb = sb0 + (i % 3) * STAGEB;
        #pragma unroll
        for (int kk = 0; kk < 2; kk++) {
            const uint32_t koff = kk * 32;
            uint32_t a[4][4], a2[4][4], b[4][4];
            #pragma unroll
            for (int mt = 0; mt < 4; mt++)
                LDSM4(a[mt], sb + SA_H + (wm*64 + mt*16)*PITCHB + loff + koff);
            #pragma unroll
            for (int p = 0; p < 4; p++)
                LDSM4(b[p], sb + SB_H + (wn*64 + p*16)*PITCHB + loff + koff);
            #pragma unroll
            for (int mt = 0; mt < 4; mt++)
                #pragma unroll
                for (int p = 0; p < 4; p++) {
                    MMA16816(c[mt][2*p],   a[mt], b[p][0], b[p][2]);
                    MMA16816(c[mt][2*p+1], a[mt], b[p][1], b[p][3]);
                }
            #pragma unroll
            for (int mt = 0; mt < 4; mt++)
                LDSM4(a2[mt], sb + SA_L + (wm*64 + mt*16)*PITCHB + loff + koff);
            #pragma unroll
            for (int mt = 0; mt < 4; mt++)
                #pragma unroll
                for (int p = 0; p < 4; p++) {
                    MMA16816(c[mt][2*p],   a2[mt], b[p][0], b[p][2]);
                    MMA16816(c[mt][2*p+1], a2[mt], b[p][1], b[p][3]);
                }
            #pragma unroll
            for (int p = 0; p < 4; p++)
                LDSM4(b[p], sb + SB_L + (wn*64 + p*16)*PITCHB + loff + koff);
            #pragma unroll
            for (int mt = 0; mt < 4; mt++)
                #pragma unroll
                for (int p = 0; p < 4; p++) {
                    MMA16816(c[mt][2*p],   a[mt], b[p][0], b[p][2]);
                    MMA16816(c[mt][2*p+1], a[mt], b[p][1], b[p][3]);
                }
        }
    }
    #undef LOAD_CHUNK

    const int rbase = m0 + wm*64 + (lane >> 2);
    const int cbase = n0 + wn*64 + (lane & 3) * 2;
    #pragma unroll
    for (int mt = 0; mt < 4; mt++) {
        #pragma unroll
        for (int nt = 0; nt < 8; nt++) {
            int row = rbase + mt*16;
            int col = cbase + nt*8;
            if (SPLIT) {
                uint32_t h0 = pack_bf2(c[mt][nt][0], c[mt][nt][1]);
                float2 f0 = unpack_bf2(h0);
                uint32_t l0 = pack_bf2(c[mt][nt][0]-f0.x, c[mt][nt][1]-f0.y);
                *(uint32_t*)&Ch[(size_t)row * DM + col] = h0;
                *(uint32_t*)&Cl[(size_t)row * DM + col] = l0;
                uint32_t h1 = pack_bf2(c[mt][nt][2], c[mt][nt][3]);
                float2 f1 = unpack_bf2(h1);
                uint32_t l1 = pack_bf2(c[mt][nt][2]-f1.x, c[mt][nt][3]-f1.y);
                *(uint32_t*)&Ch[(size_t)(row+8) * DM + col] = h1;
                *(uint32_t*)&Cl[(size_t)(row+8) * DM + col] = l1;
            } else {
                float2 v0; v0.x = c[mt][nt][0]; v0.y = c[mt][nt][1];
                float2 v1; v1.x = c[mt][nt][2]; v1.y = c[mt][nt][3];
                *(float2*)&C[(size_t)row * DM + col]       = v0;
                *(float2*)&C[(size_t)(row + 8) * DM + col] = v1;
            }
        }
    }
}

// ============== MMA flash attention (bf16 hi/lo, 3-pass) =====================
// BQ=128 q rows per CTA (8 warps x 16), BK=64 keys per iter, 2-stage cp.async.
#define BQ 128
#define BK 64
#define PB 144                   // smem pitch bytes (64 bf16 + 8 pad)
#define SQ_H 0
#define SQ_L 18432
#define STG0 36864
#define STGSZ 36864              // per stage: KH@0 KL@9216 VH@18432 VL@27648
#define ATTN_SMEM 110592

__global__ __launch_bounds__(256, 1) void attn_mma() {
    extern __shared__ char smc[];
    const uint32_t sb = smem_u32(smc);
    const int tid  = threadIdx.x;
    const int w    = tid >> 5;
    const int lane = tid & 31;
    const int bh = blockIdx.y, h = bh & 15, b = bh >> 4;
    const int q0 = blockIdx.x * BQ;
    const int rowbase = b * SEQ;

    const __nv_bfloat16* gqh = (const __nv_bfloat16*)g_qh;
    const __nv_bfloat16* gql = (const __nv_bfloat16*)g_ql;
    const __nv_bfloat16* gkh = (const __nv_bfloat16*)g_kh;
    const __nv_bfloat16* gkl = (const __nv_bfloat16*)g_kl;
    const __nv_bfloat16* gvh = (const __nv_bfloat16*)g_vh;
    const __nv_bfloat16* gvl = (const __nv_bfloat16*)g_vl;

    // Q tile -> smem (hi/lo), once
    #pragma unroll
    for (int t = 0; t < 8; t++) {
        int idx = tid + t*256;               // 0..2047
        int arr = idx >> 10;                 // 0 hi, 1 lo
        int i2  = idx & 1023;
        int r   = i2 >> 3, cc = i2 & 7;
        const __nv_bfloat16* src = (arr ? gql : gqh)
            + (size_t)(rowbase + q0 + r) * DM + h*DH + cc*8;
        cp_async16(sb + (arr ? SQ_L : SQ_H) + r*PB + cc*16, src);
    }

    #define LOADKV(j) do { \
        const uint32_t st_ = sb + STG0 + ((j) & 1) * STGSZ; \
        const int kk0 = (j) * BK; \
        _Pragma("unroll") \
        for (int t = 0; t < 8; t++) { \
            int idx = tid + t*256; \
            int arr = idx >> 9; int i2 = idx & 511; \
            int r = i2 >> 3, cc = i2 & 7; \
            const __nv_bfloat16* srcp = (arr == 0) ? gkh : (arr == 1) ? gkl : (arr == 2) ? gvh : gvl; \
            srcp += (size_t)(rowbase + kk0 + r) * DM + h*DH + cc*8; \
            cp_async16(st_ + arr*9216 + r*PB + cc*16, srcp); \
        } \
    } while (0)

    LOADKV(0);
    CP_COMMIT();                              // group0 = Q + stage0

    const uint32_t loff = (lane & 15) * PB + (lane >> 4) * 16;
    uint32_t qfh[4][4], qfl[4][4];

    float o[8][4];
    #pragma unroll
    for (int dt = 0; dt < 8; dt++)
        #pragma unroll
        for (int q = 0; q < 4; q++) o[dt][q] = 0.0f;
    float m0r = -1e30f, m1r = -1e30f, l0r = 0.0f, l1r = 0.0f;

    const float* bt = g_bias + h * 4096;
    const int row0 = lane >> 2;
    const int col2 = (lane & 3) * 2;

    #pragma unroll 1
    for (int i = 0; i < SEQ/BK; i++) {
        if (i + 1 < SEQ/BK) LOADKV(i + 1);
        CP_COMMIT();
        CP_WAIT(1);
        __syncthreads();

        if (i == 0) {
            #pragma unroll
            for (int ks = 0; ks < 4; ks++) {
                LDSM4(qfh[ks], sb + SQ_H + w*16*PB + loff + ks*32);
                LDSM4(qfl[ks], sb + SQ_L + w*16*PB + loff + ks*32);
            }
        }

        const uint32_t st = sb + STG0 + (i & 1) * STGSZ;

        // ---- S = Q K^T (hi/lo 3-pass), 16x64 per warp ----
        float s[8][4];
        #pragma unroll
        for (int nt = 0; nt < 8; nt++)
            #pragma unroll
            for (int q = 0; q < 4; q++) s[nt][q] = 0.0f;

        #pragma unroll
        for (int ks = 0; ks < 4; ks++) {
            #pragma unroll
            for (int np = 0; np < 4; np++) {
                uint32_t bh4[4], bl4[4];
                LDSM4(bh4, st + (np*16)*PB + loff + ks*32);
                LDSM4(bl4, st + 9216 + (np*16)*PB + loff + ks*32);
                MMA16816(s[2*np],   qfh[ks], bh4[0], bh4[2]);
                MMA16816(s[2*np+1], qfh[ks], bh4[1], bh4[3]);
                MMA16816(s[2*np],   qfl[ks], bh4[0], bh4[2]);
                MMA16816(s[2*np+1], qfl[ks], bh4[1], bh4[3]);
                MMA16816(s[2*np],   qfh[ks], bl4[0], bl4[2]);
                MMA16816(s[2*np+1], qfh[ks], bl4[1], bl4[3]);
            }
        }

        // ---- + relative position bias ----
        const float* bp0 = bt + 2048 + i*BK + col2 - (q0 + w*16 + row0);
        #pragma unroll
        for (int nt = 0; nt < 8; nt++) {
            s[nt][0] += __ldg(bp0 + nt*8);
            s[nt][1] += __ldg(bp0 + nt*8 + 1);
            s[nt][2] += __ldg(bp0 + nt*8 - 8);
            s[nt][3] += __ldg(bp0 + nt*8 - 7);
        }

        // ---- online softmax (per-thread rows row0, row0+8; quad reduce) ----
        float t0 = -1e30f, t1 = -1e30f;
        #pragma unroll
        for (int nt = 0; nt < 8; nt++) {
            t0 = fmaxf(t0, fmaxf(s[nt][0], s[nt][1]));
            t1 = fmaxf(t1, fmaxf(s[nt][2], s[nt][3]));
        }
        t0 = fmaxf(t0, __shfl_xor_sync(0xffffffffu, t0, 1));
        t0 = fmaxf(t0, __shfl_xor_sync(0xffffffffu, t0, 2));
        t1 = fmaxf(t1, __shfl_xor_sync(0xffffffffu, t1, 1));
        t1 = fmaxf(t1, __shfl_xor_sync(0xffffffffu, t1, 2));
        float mn0 = fmaxf(m0r, t0), mn1 = fmaxf(m1r, t1);
        float a0 = expp(m0r - mn0), a1 = expp(m1r - mn1);
        m0r = mn0; m1r = mn1;

        float ps0 = 0.0f, ps1 = 0.0f;
        #pragma unroll
        for (int nt = 0; nt < 8; nt++) {
            s[nt][0] = expp(s[nt][0] - mn0);
            s[nt][1] = expp(s[nt][1] - mn0);
            s[nt][2] = expp(s[nt][2] - mn1);
            s[nt][3] = expp(s[nt][3] - mn1);
            ps0 += s[nt][0] + s[nt][1];
            ps1 += s[nt][2] + s[nt][3];
        }
        ps0 += __shfl_xor_sync(0xffffffffu, ps0, 1);
        ps0 += __shfl_xor_sync(0xffffffffu, ps0, 2);
        ps1 += __shfl_xor_sync(0xffffffffu, ps1, 1);
        ps1 += __shfl_xor_sync(0xffffffffu, ps1, 2);
        l0r = l0r * a0 + ps0;
        l1r = l1r * a1 + ps1;
        #pragma unroll
        for (int dt = 0; dt < 8; dt++) {
            o[dt][0] *= a0; o[dt][1] *= a0;
            o[dt][2] *= a1; o[dt][3] *= a1;
        }

        // ---- O += P V (hi/lo 3-pass), P frags built per k-step ----
        #pragma unroll
        for (int ks = 0; ks < 4; ks++) {
            uint32_t ah4[4], al4[4];
            #pragma unroll
            for (int q = 0; q < 4; q++) {
                int nt = 2*ks + (q >> 1);
                float x = s[nt][(q & 1) * 2];
                float y = s[nt][(q & 1) * 2 + 1];
                ah4[q] = pack_bf2(x, y);
                float2 hf = unpack_bf2(ah4[q]);
                al4[q] = pack_bf2(x - hf.x, y - hf.y);
            }
            #pragma unroll
            for (int dp = 0; dp < 4; dp++) {
                uint32_t vh4[4], vl4[4];
                LDSM4T(vh4, st + 18432 + (ks*16 + (lane & 15))*PB + dp*32 + (lane >> 4)*16);
                LDSM4T(vl4, st + 27648 + (ks*16 + (lane & 15))*PB + dp*32 + (lane >> 4)*16);
                MMA16816(o[2*dp],   ah4, vh4[0], vh4[1]);
                MMA16816(o[2*dp+1], ah4, vh4[2], vh4[3]);
                MMA16816(o[2*dp],   al4, vh4[0], vh4[1]);
                MMA16816(o[2*dp+1], al4, vh4[2], vh4[3]);
                MMA16816(o[2*dp],   ah4, vl4[0], vl4[1]);
                MMA16816(o[2*dp+1], ah4, vl4[2], vl4[3]);
            }
        }
        __syncthreads();
    }
    #undef LOADKV

    // ---- epilogue: normalize, split to bf16 hi/lo ----
    float inv0 = 1.0f / l0r, inv1 = 1.0f / l1r;
    __nv_bfloat16* oh = (__nv_bfloat16*)g_ah;
    __nv_bfloat16* ol = (__nv_bfloat16*)g_al;
    const size_t gr0 = (size_t)(rowbase + q0 + w*16 + row0) * DM + h*DH;
    const size_t gr1 = gr0 + 8 * DM;
    #pragma unroll
    for (int dt = 0; dt < 8; dt++) {
        int col = dt*8 + col2;
        float x0 = o[dt][0]*inv0, y0 = o[dt][1]*inv0;
        uint32_t h0 = pack_bf2(x0, y0);
        float2 f0 = unpack_bf2(h0);
        *(uint32_t*)&oh[gr0 + col] = h0;
        *(uint32_t*)&ol[gr0 + col] = pack_bf2(x0 - f0.x, y0 - f0.y);
        float x1 = o[dt][2]*inv1, y1 = o[dt][3]*inv1;
        uint32_t h1 = pack_bf2(x1, y1);
        float2 f1 = unpack_bf2(h1);
        *(uint32_t*)&oh[gr1 + col] = h1;
        *(uint32_t*)&ol[gr1 + col] = pack_bf2(x1 - f1.x, y1 - f1.y);
    }
}

// ---------------- launch -----------------------------------------------------
extern "C" void kernel_launch(void* const* d_in, const int* in_sizes, int n_in,
                              void* d_out, int out_size) {
    const float* hidden = (const float*)d_in[0];
    const float* Wq     = (const float*)d_in[1];
    const float* Wk     = (const float*)d_in[2];
    const float* Wv     = (const float*)d_in[3];
    const float* Wo     = (const float*)d_in[4];
    const float* relb   = (const float*)d_in[5];
    float* out = (float*)d_out;

    void *phh, *phl, *pah, *pal, *pwh, *pwl;
    void *pqh, *pql, *pkh, *pkl, *pvh, *pvl;
    cudaGetSymbolAddress(&phh, g_hh);
    cudaGetSymbolAddress(&phl, g_hl);
    cudaGetSymbolAddress(&pah, g_ah);
    cudaGetSymbolAddress(&pal, g_al);
    cudaGetSymbolAddress(&pwh, g_wh);
    cudaGetSymbolAddress(&pwl, g_wl);
    cudaGetSymbolAddress(&pqh, g_qh);
    cudaGetSymbolAddress(&pql, g_ql);
    cudaGetSymbolAddress(&pkh, g_kh);
    cudaGetSymbolAddress(&pkl, g_kl);
    cudaGetSymbolAddress(&pvh, g_vh);
    cudaGetSymbolAddress(&pvl, g_vl);

    __nv_bfloat16* hh = (__nv_bfloat16*)phh;
    __nv_bfloat16* hl = (__nv_bfloat16*)phl;
    __nv_bfloat16* ah = (__nv_bfloat16*)pah;
    __nv_bfloat16* al = (__nv_bfloat16*)pal;
    __nv_bfloat16* wh = (__nv_bfloat16*)pwh;
    __nv_bfloat16* wl = (__nv_bfloat16*)pwl;

    convert_split<<<(MROWS*DM/4)/256, 256>>>(hidden, hh, hl);
    dim3 tg(DM/32, DM/32), tb(32, 8);
    convert_w_t<<<tg, tb>>>(Wq, wh + 0*DM*DM, wl + 0*DM*DM);
    convert_w_t<<<tg, tb>>>(Wk, wh + 1*DM*DM, wl + 1*DM*DM);
    convert_w_t<<<tg, tb>>>(Wv, wh + 2*DM*DM, wl + 2*DM*DM);
    convert_w_t<<<tg, tb>>>(Wo, wh + 3*DM*DM, wl + 3*DM*DM);
    bias_kernel<<<NH, 256>>>(relb);

    cudaFuncSetAttribute(gemm_mma<1>, cudaFuncAttributeMaxDynamicSharedMemorySize, GEMM_SMEM);
    cudaFuncSetAttribute(gemm_mma<0>, cudaFuncAttributeMaxDynamicSharedMemorySize, GEMM_SMEM);
    dim3 gg(DM/256, MROWS/128);   // (4, 32)
    gemm_mma<1><<<gg, 256, GEMM_SMEM>>>(hh, hl, wh + 0*DM*DM, wl + 0*DM*DM,
                                        nullptr, (__nv_bfloat16*)pqh, (__nv_bfloat16*)pql);
    gemm_mma<1><<<gg, 256, GEMM_SMEM>>>(hh, hl, wh + 1*DM*DM, wl + 1*DM*DM,
                                        nullptr, (__nv_bfloat16*)pkh, (__nv_bfloat16*)pkl);
    gemm_mma<1><<<gg, 256, GEMM_SMEM>>>(hh, hl, wh + 2*DM*DM, wl + 2*DM*DM,
                                        nullptr, (__nv_bfloat16*)pvh, (__nv_bfloat16*)pvl);

    cudaFuncSetAttribute(attn_mma, cudaFuncAttributeMaxDynamicSharedMemorySize, ATTN_SMEM);
    attn_mma<<<dim3(SEQ/BQ, BATCH*NH), 256, ATTN_SMEM>>>();

    gemm_mma<0><<<gg, 256, GEMM_SMEM>>>(ah, al, wh + 3*DM*DM, wl + 3*DM*DM,
                                        out, nullptr, nullptr);
}

// round 5
// speedup vs baseline: 2.4575x; 1.0019x over previous
#include <cuda_runtime.h>
#include <cuda_bf16.h>
#include <math.h>
#include <stdint.h>

#define SEQ   2048
#define NH    16
#define DH    64
#define DM    1024
#define DM3   3072
#define BATCH 2
#define MROWS (BATCH*SEQ)   // 4096
#define GRID_SK 148

// ---------------- scratch (device globals; no allocations allowed) ----------
__device__ float g_bias[NH*4096];            // per-head bias vs (j-i)+2048
__device__ unsigned short g_hh[MROWS*DM];    // hidden bf16 hi
__device__ unsigned short g_hl[MROWS*DM];    // hidden bf16 lo
__device__ unsigned short g_xh[MROWS*DM3];   // fused QKV out hi [row][3072]
__device__ unsigned short g_xl[MROWS*DM3];
__device__ unsigned short g_ah[MROWS*DM];    // attn out bf16 hi
__device__ unsigned short g_al[MROWS*DM];
__device__ unsigned short g_wh[4][DM*DM];    // W transposed [n][k] bf16 hi (q,k,v,o)
__device__ unsigned short g_wl[4][DM*DM];
__device__ float g_scr[GRID_SK][128*256];    // stream-K partial tiles
__device__ int   g_flag[GRID_SK+1];          // stream-K arrival flags (self-resetting)

// ======================= helpers =============================================
__device__ __forceinline__ uint32_t smem_u32(const void* p) {
    uint32_t a;
    asm("{ .reg .u64 t; cvta.to.shared.u64 t, %1; cvt.u32.u64 %0, t; }" : "=r"(a) : "l"(p));
    return a;
}
__device__ __forceinline__ void cp_async16(uint32_t dst, const void* src) {
    asm volatile("cp.async.cg.shared.global [%0], [%1], 16;" :: "r"(dst), "l"(src));
}
#define CP_COMMIT() asm volatile("cp.async.commit_group;" ::: "memory")
#define CP_WAIT(N)  asm volatile("cp.async.wait_group %0;" :: "n"(N) : "memory")

#define LDSM4(r, addr) \
    asm volatile("ldmatrix.sync.aligned.m8n8.x4.shared.b16 {%0,%1,%2,%3}, [%4];" \
        : "=r"((r)[0]), "=r"((r)[1]), "=r"((r)[2]), "=r"((r)[3]) : "r"(addr))
#define LDSM4T(r, addr) \
    asm volatile("ldmatrix.sync.aligned.m8n8.x4.trans.shared.b16 {%0,%1,%2,%3}, [%4];" \
        : "=r"((r)[0]), "=r"((r)[1]), "=r"((r)[2]), "=r"((r)[3]) : "r"(addr))

#define MMA16816(c, a, b0, b1) \
    asm volatile("mma.sync.aligned.m16n8k16.row.col.f32.bf16.bf16.f32 " \
        "{%0,%1,%2,%3}, {%4,%5,%6,%7}, {%8,%9}, {%0,%1,%2,%3};" \
        : "+f"((c)[0]), "+f"((c)[1]), "+f"((c)[2]), "+f"((c)[3]) \
        : "r"((a)[0]), "r"((a)[1]), "r"((a)[2]), "r"((a)[3]), "r"(b0), "r"(b1))

__device__ __forceinline__ uint32_t pack_bf2(float x, float y) {
    __nv_bfloat162 t = __floats2bfloat162_rn(x, y);
    return *(uint32_t*)&t;
}
__device__ __forceinline__ float2 unpack_bf2(uint32_t u) {
    __nv_bfloat162 t = *(__nv_bfloat162*)&u;
    return __bfloat1622float2(t);
}

// fast exp on the FMA pipe (args <= 0; clamp keeps scale exponent valid)
__device__ __forceinline__ float expp(float x) {
    x = fmaxf(x, -80.0f);
    float y = x * 1.4426950408889634f;
    float t = y + 12582912.0f;
    int   n = __float_as_int(t) - 0x4B400000;
    float f = y - (t - 12582912.0f);
    float g = f * 0.6931471805599453f;
    float p = fmaf(g, 0.008333333f, 0.041666668f);
    p = fmaf(p, g, 0.16666667f);
    p = fmaf(p, g, 0.5f);
    p = fmaf(p, g, 1.0f);
    p = fmaf(p, g, 1.0f);
    return p * __int_as_float((n + 127) << 23);
}

// ---------------- relative-position bias table ------------------------------
__global__ void bias_kernel(const float* __restrict__ rel_bias) {
    int h = blockIdx.x;
    for (int i = threadIdx.x; i < 4096; i += blockDim.x) {
        int delta = i - 2048;
        int rb = (delta > 0) ? 16 : 0;
        int ar = delta < 0 ? -delta : delta;
        int bucket;
        if (ar < 8) {
            bucket = rb + ar;
        } else {
            int l = 8 + (int)(2.0f * log2f((float)ar * 0.125f));
            bucket = rb + (l > 15 ? 15 : l);
        }
        g_bias[h*4096 + i] = rel_bias[bucket*NH + h];
    }
}

// ---------------- fp32 -> bf16 hi/lo split (elementwise) --------------------
__global__ void convert_split(const float* __restrict__ x,
                              __nv_bfloat16* __restrict__ oh,
                              __nv_bfloat16* __restrict__ ol) {
    int i = blockIdx.x * blockDim.x + threadIdx.x;
    float4 v = ((const float4*)x)[i];
    __nv_bfloat16 h0 = __float2bfloat16_rn(v.x);
    __nv_bfloat16 h1 = __float2bfloat16_rn(v.y);
    __nv_bfloat16 h2 = __float2bfloat16_rn(v.z);
    __nv_bfloat16 h3 = __float2bfloat16_rn(v.w);
    __nv_bfloat16 l0 = __float2bfloat16_rn(v.x - __bfloat162float(h0));
    __nv_bfloat16 l1 = __float2bfloat16_rn(v.y - __bfloat162float(h1));
    __nv_bfloat16 l2 = __float2bfloat16_rn(v.z - __bfloat162float(h2));
    __nv_bfloat16 l3 = __float2bfloat16_rn(v.w - __bfloat162float(h3));
    __nv_bfloat162* ph = (__nv_bfloat162*)(oh + 4*(size_t)i);
    __nv_bfloat162* pl = (__nv_bfloat162*)(ol + 4*(size_t)i);
    ph[0] = __halves2bfloat162(h0, h1);
    ph[1] = __halves2bfloat162(h2, h3);
    pl[0] = __halves2bfloat162(l0, l1);
    pl[1] = __halves2bfloat162(l2, l3);
}

// -------- all 4 W: fp32 [k][n] -> bf16 hi/lo transposed [n][k], one launch ---
__global__ void convert_w_all(const float* __restrict__ W0, const float* __restrict__ W1,
                              const float* __restrict__ W2, const float* __restrict__ W3) {
    __shared__ float t[32][33];
    int z = blockIdx.z;
    const float* W = (z == 0) ? W0 : (z == 1) ? W1 : (z == 2) ? W2 : W3;
    __nv_bfloat16* oh = (__nv_bfloat16*)g_wh + (size_t)z * DM * DM;
    __nv_bfloat16* ol = (__nv_bfloat16*)g_wl + (size_t)z * DM * DM;
    int tx = threadIdx.x, ty = threadIdx.y;
    int n0 = blockIdx.x * 32, k0 = blockIdx.y * 32;
    #pragma unroll
    for (int j = 0; j < 32; j += 8)
        t[ty + j][tx] = W[(size_t)(k0 + ty + j) * DM + n0 + tx];
    __syncthreads();
    #pragma unroll
    for (int j = 0; j < 32; j += 8) {
        float v = t[tx][ty + j];
        size_t o = (size_t)(n0 + ty + j) * DM + k0 + tx;
        __nv_bfloat16 h = __float2bfloat16_rn(v);
        oh[o] = h;
        ol[o] = __float2bfloat16_rn(v - __bfloat162float(h));
    }
}

// ============== stream-K HMMA GEMM: C[4096 x N] = (Ah+Al)(Bh+Bl)^T ==========
// Tile 128 x TN, chunks of K=32, perfectly balanced chunk ranges over grid.
// Tiles split across <=2 CTAs; tail-owner posts fp32 partial, head-owner adds.
#define PITCHB 80

template<int TN, int SPLIT>
__global__ __launch_bounds__(256, 1) void gemm_sk(
    const __nv_bfloat16* __restrict__ Ah, const __nv_bfloat16* __restrict__ Al,
    const __nv_bfloat16* __restrict__ Bh, const __nv_bfloat16* __restrict__ Bl,
    float* __restrict__ C,
    __nv_bfloat16* __restrict__ Ch, __nv_bfloat16* __restrict__ Cl,
    int NBLK, int NT, int ldc)
{
    constexpr int NFR = TN / 32;                // accum n-frags per thread
    constexpr int SAH = 0;
    constexpr int SAL = 128 * PITCHB;
    constexpr int SBH = 2 * 128 * PITCHB;
    constexpr int SBL = SBH + TN * PITCHB;
    constexpr int STG = SBL + TN * PITCHB;      // stage bytes

    extern __shared__ char smem[];
    const uint32_t sb0 = smem_u32(smem);
    const int tid  = threadIdx.x;
    const int wid  = tid >> 5;
    const int lane = tid & 31;
    const int wm   = wid >> 2;
    const int wn   = wid & 3;
    const int cta  = blockIdx.x;
    const int G    = gridDim.x;

    const int total = NT * 32;
    const int s = (int)(((long long)cta       * total) / G);
    const int e = (int)(((long long)(cta + 1) * total) / G);

    const uint32_t lrow  = lane & 15;
    const uint32_t lhalf = (lane >> 4) & 1;
    const uint32_t loff  = lrow * PITCHB + lhalf * 16;

    float acc[4][NFR][4];
    #pragma unroll
    for (int mt = 0; mt < 4; mt++)
        #pragma unroll
        for (int nt = 0; nt < NFR; nt++)
            #pragma unroll
            for (int q = 0; q < 4; q++) acc[mt][nt][q] = 0.0f;
    float* af = &acc[0][0][0];
    constexpr int ACCN = 16 * NFR;

    // ---- chunk loader (addresses derived from global chunk id) ----
    auto load_chunk = [&](int c) {
        int t  = c >> 5, kc = c & 31;
        int m0 = (t / NBLK) * 128;
        int n0 = (t % NBLK) * TN;
        int k0 = kc * 32;
        const uint32_t sb = sb0 + ((c - s) % 3) * STG;
        #pragma unroll
        for (int tt = 0; tt < 2; tt++) {
            int idx = tid + tt*256; int r = idx >> 2, cc = idx & 3;
            cp_async16(sb + SAH + r*PITCHB + cc*16, Ah + (size_t)(m0+r)*DM + k0 + cc*8);
            cp_async16(sb + SAL + r*PITCHB + cc*16, Al + (size_t)(m0+r)*DM + k0 + cc*8);
        }
        #pragma unroll
        for (int tt = 0; tt < TN/64; tt++) {
            int idx = tid + tt*256; int r = idx >> 2, cc = idx & 3;
            cp_async16(sb + SBH + r*PITCHB + cc*16, Bh + (size_t)(n0+r)*DM + k0 + cc*8);
            cp_async16(sb + SBL + r*PITCHB + cc*16, Bl + (size_t)(n0+r)*DM + k0 + cc*8);
        }
    };

    // ---- epilogue: write tile t from acc ----
    auto direct_epi = [&](int t) {
        int m0 = (t / NBLK) * 128;
        int n0 = (t % NBLK) * TN;
        const int rbase = m0 + wm*64 + (lane >> 2);
        const int cbase = n0 + wn*(TN/4) + (lane & 3) * 2;
        #pragma unroll
        for (int mt = 0; mt < 4; mt++) {
            #pragma unroll
            for (int nt = 0; nt < NFR; nt++) {
                int row = rbase + mt*16;
                int col = cbase + nt*8;
                if (SPLIT) {
                    uint32_t h0 = pack_bf2(acc[mt][nt][0], acc[mt][nt][1]);
                    float2 f0 = unpack_bf2(h0);
                    *(uint32_t*)&Ch[(size_t)row * ldc + col] = h0;
                    *(uint32_t*)&Cl[(size_t)row * ldc + col] =
                        pack_bf2(acc[mt][nt][0]-f0.x, acc[mt][nt][1]-f0.y);
                    uint32_t h1 = pack_bf2(acc[mt][nt][2], acc[mt][nt][3]);
                    float2 f1 = unpack_bf2(h1);
                    *(uint32_t*)&Ch[(size_t)(row+8) * ldc + col] = h1;
                    *(uint32_t*)&Cl[(size_t)(row+8) * ldc + col] =
                        pack_bf2(acc[mt][nt][2]-f1.x, acc[mt][nt][3]-f1.y);
                } else {
                    float2 v0; v0.x = acc[mt][nt][0]; v0.y = acc[mt][nt][1];
                    float2 v1; v1.x = acc[mt][nt][2]; v1.y = acc[mt][nt][3];
                    *(float2*)&C[(size_t)row * ldc + col]       = v0;
                    *(float2*)&C[(size_t)(row + 8) * ldc + col] = v1;
                }
            }
        }
    };

    // ---- 2-deep prefetch ----
    load_chunk(s); CP_COMMIT();
    if (s + 1 < e) { load_chunk(s + 1); CP_COMMIT(); }

    #pragma unroll 1
    for (int c = s; c < e; c++) {
        if (c + 1 < e) { CP_WAIT(1); } else { CP_WAIT(0); }
        __syncthreads();
        if (c + 2 < e) { load_chunk(c + 2); CP_COMMIT(); }

        // ---- MMA on chunk c ----
        const uint32_t sb = sb0 + ((c - s) % 3) * STG;
        #pragma unroll
        for (int kk = 0; kk < 2; kk++) {
            const uint32_t koff = kk * 32;
            uint32_t a[4][4], a2[4][4], b[TN/64][4];
            #pragma unroll
            for (int mt = 0; mt < 4; mt++)
                LDSM4(a[mt], sb + SAH + (wm*64 + mt*16)*PITCHB + loff + koff);
            #pragma unroll
            for (int p = 0; p < TN/64; p++)
                LDSM4(b[p], sb + SBH + (wn*(TN/4) + p*16)*PITCHB + loff + koff);
            #pragma unroll
            for (int mt = 0; mt < 4; mt++)
                #pragma unroll
                for (int p = 0; p < TN/64; p++) {
                    MMA16816(acc[mt][2*p],   a[mt], b[p][0], b[p][2]);
                    MMA16816(acc[mt][2*p+1], a[mt], b[p][1], b[p][3]);
                }
            #pragma unroll
            for (int mt = 0; mt < 4; mt++)
                LDSM4(a2[mt], sb + SAL + (wm*64 + mt*16)*PITCHB + loff + koff);
            #pragma unroll
            for (int mt = 0; mt < 4; mt++)
                #pragma unroll
                for (int p = 0; p < TN/64; p++) {
                    MMA16816(acc[mt][2*p],   a2[mt], b[p][0], b[p][2]);
                    MMA16816(acc[mt][2*p+1], a2[mt], b[p][1], b[p][3]);
                }
            #pragma unroll
            for (int p = 0; p < TN/64; p++)
                LDSM4(b[p], sb + SBL + (wn*(TN/4) + p*16)*PITCHB + loff + koff);
            #pragma unroll
            for (int mt = 0; mt < 4; mt++)
                #pragma unroll
                for (int p = 0; p < TN/64; p++) {
                    MMA16816(acc[mt][2*p],   a[mt], b[p][0], b[p][2]);
                    MMA16816(acc[mt][2*p+1], a[mt], b[p][1], b[p][3]);
                }
        }

        // ---- tile boundary handling ----
        const int t = c >> 5;
        if ((c & 31) == 31) {
            if (t * 32 >= s) {
                direct_epi(t);                    // full tile owned by this CTA
            } else {
                // tail partial: post to scratch + flag
                float* slot = g_scr[cta] + (size_t)tid * ACCN;
                #pragma unroll
                for (int i = 0; i < ACCN; i += 4)
                    *(float4*)&slot[i] = *(float4*)&af[i];
                __threadfence();
                __syncthreads();
                if (tid == 0) atomicExch(&g_flag[cta], 1);
            }
            #pragma unroll
            for (int i = 0; i < ACCN; i++) af[i] = 0.0f;
        } else if (c == e - 1) {
            // head of a split tile: wait for neighbor's tail partial, add, write
            if (tid == 0) {
                while (atomicAdd(&g_flag[cta + 1], 0) == 0) { __nanosleep(64); }
                atomicExch(&g_flag[cta + 1], 0);   // self-reset for replay
                __threadfence();
            }
            __syncthreads();
            const float* slot = g_scr[cta + 1] + (size_t)tid * ACCN;
            #pragma unroll
            for (int i = 0; i < ACCN; i += 4) {
                float4 v = __ldcv((const float4*)&slot[i]);
                af[i+0] += v.x; af[i+1] += v.y; af[i+2] += v.z; af[i+3] += v.w;
            }
            direct_epi(t);
        }
    }
}

// ============== MMA flash attention (bf16 hi/lo, 3-pass) =====================
#define BQ 128
#define BK 64
#define PB 144
#define SQ_H 0
#define SQ_L 18432
#define STG0 36864
#define STGSZ 36864
#define ATTN_SMEM 110592

__global__ __launch_bounds__(256, 1) void attn_mma() {
    extern __shared__ char smc[];
    const uint32_t sb = smem_u32(smc);
    const int tid  = threadIdx.x;
    const int w    = tid >> 5;
    const int lane = tid & 31;
    const int bh = blockIdx.y, h = bh & 15, b = bh >> 4;
    const int q0 = blockIdx.x * BQ;
    const int rowbase = b * SEQ;

    const __nv_bfloat16* gxh = (const __nv_bfloat16*)g_xh;
    const __nv_bfloat16* gxl = (const __nv_bfloat16*)g_xl;

    // Q tile -> smem (hi/lo), once. q at col offset 0.
    #pragma unroll
    for (int t = 0; t < 8; t++) {
        int idx = tid + t*256;
        int arr = idx >> 10;
        int i2  = idx & 1023;
        int r   = i2 >> 3, cc = i2 & 7;
        const __nv_bfloat16* src = (arr ? gxl : gxh)
            + (size_t)(rowbase + q0 + r) * DM3 + h*DH + cc*8;
        cp_async16(sb + (arr ? SQ_L : SQ_H) + r*PB + cc*16, src);
    }

    // K at col 1024, V at col 2048 of the fused buffer
    #define LOADKV(j) do { \
        const uint32_t st_ = sb + STG0 + ((j) & 1) * STGSZ; \
        const int kk0 = (j) * BK; \
        _Pragma("unroll") \
        for (int t = 0; t < 8; t++) { \
            int idx = tid + t*256; \
            int arr = idx >> 9; int i2 = idx & 511; \
            int r = i2 >> 3, cc = i2 & 7; \
            const __nv_bfloat16* srcp = ((arr & 1) ? gxl : gxh) + ((arr >> 1) + 1) * 1024; \
            srcp += (size_t)(rowbase + kk0 + r) * DM3 + h*DH + cc*8; \
            cp_async16(st_ + arr*9216 + r*PB + cc*16, srcp); \
        } \
    } while (0)

    LOADKV(0);
    CP_COMMIT();

    const uint32_t loff = (lane & 15) * PB + (lane >> 4) * 16;
    uint32_t qfh[4][4], qfl[4][4];

    float o[8][4];
    #pragma unroll
    for (int dt = 0; dt < 8; dt++)
        #pragma unroll
        for (int q = 0; q < 4; q++) o[dt][q] = 0.0f;
    float m0r = -1e30f, m1r = -1e30f, l0r = 0.0f, l1r = 0.0f;

    const float* bt = g_bias + h * 4096;
    const int row0 = lane >> 2;
    const int col2 = (lane & 3) * 2;

    #pragma unroll 1
    for (int i = 0; i < SEQ/BK; i++) {
        if (i + 1 < SEQ/BK) LOADKV(i + 1);
        CP_COMMIT();
        CP_WAIT(1);
        __syncthreads();

        if (i == 0) {
            #pragma unroll
            for (int ks = 0; ks < 4; ks++) {
                LDSM4(qfh[ks], sb + SQ_H + w*16*PB + loff + ks*32);
                LDSM4(qfl[ks], sb + SQ_L + w*16*PB + loff + ks*32);
            }
        }

        const uint32_t st = sb + STG0 + (i & 1) * STGSZ;

        float s[8][4];
        #pragma unroll
        for (int nt = 0; nt < 8; nt++)
            #pragma unroll
            for (int q = 0; q < 4; q++) s[nt][q] = 0.0f;

        #pragma unroll
        for (int ks = 0; ks < 4; ks++) {
            #pragma unroll
            for (int np = 0; np < 4; np++) {
                uint32_t bh4[4], bl4[4];
                LDSM4(bh4, st + (np*16)*PB + loff + ks*32);
                LDSM4(bl4, st + 9216 + (np*16)*PB + loff + ks*32);
                MMA16816(s[2*np],   qfh[ks], bh4[0], bh4[2]);
                MMA16816(s[2*np+1], qfh[ks], bh4[1], bh4[3]);
                MMA16816(s[2*np],   qfl[ks], bh4[0], bh4[2]);
                MMA16816(s[2*np+1], qfl[ks], bh4[1], bh4[3]);
                MMA16816(s[2*np],   qfh[ks], bl4[0], bl4[2]);
                MMA16816(s[2*np+1], qfh[ks], bl4[1], bl4[3]);
            }
        }

        const float* bp0 = bt + 2048 + i*BK + col2 - (q0 + w*16 + row0);
        #pragma unroll
        for (int nt = 0; nt < 8; nt++) {
            s[nt][0] += __ldg(bp0 + nt*8);
            s[nt][1] += __ldg(bp0 + nt*8 + 1);
            s[nt][2] += __ldg(bp0 + nt*8 - 8);
            s[nt][3] += __ldg(bp0 + nt*8 - 7);
        }

        float t0 = -1e30f, t1 = -1e30f;
        #pragma unroll
        for (int nt = 0; nt < 8; nt++) {
            t0 = fmaxf(t0, fmaxf(s[nt][0], s[nt][1]));
            t1 = fmaxf(t1, fmaxf(s[nt][2], s[nt][3]));
        }
        t0 = fmaxf(t0, __shfl_xor_sync(0xffffffffu, t0, 1));
        t0 = fmaxf(t0, __shfl_xor_sync(0xffffffffu, t0, 2));
        t1 = fmaxf(t1, __shfl_xor_sync(0xffffffffu, t1, 1));
        t1 = fmaxf(t1, __shfl_xor_sync(0xffffffffu, t1, 2));
        float mn0 = fmaxf(m0r, t0), mn1 = fmaxf(m1r, t1);
        float a0 = expp(m0r - mn0), a1 = expp(m1r - mn1);
        m0r = mn0; m1r = mn1;

        float ps0 = 0.0f, ps1 = 0.0f;
        #pragma unroll
        for (int nt = 0; nt < 8; nt++) {
            s[nt][0] = expp(s[nt][0] - mn0);
            s[nt][1] = expp(s[nt][1] - mn0);
            s[nt][2] = expp(s[nt][2] - mn1);
            s[nt][3] = expp(s[nt][3] - mn1);
            ps0 += s[nt][0] + s[nt][1];
            ps1 += s[nt][2] + s[nt][3];
        }
        ps0 += __shfl_xor_sync(0xffffffffu, ps0, 1);
        ps0 += __shfl_xor_sync(0xffffffffu, ps0, 2);
        ps1 += __shfl_xor_sync(0xffffffffu, ps1, 1);
        ps1 += __shfl_xor_sync(0xffffffffu, ps1, 2);
        l0r = l0r * a0 + ps0;
        l1r = l1r * a1 + ps1;
        #pragma unroll
        for (int dt = 0; dt < 8; dt++) {
            o[dt][0] *= a0; o[dt][1] *= a0;
            o[dt][2] *= a1; o[dt][3] *= a1;
        }

        #pragma unroll
        for (int ks = 0; ks < 4; ks++) {
            uint32_t ah4[4], al4[4];
            #pragma unroll
            for (int q = 0; q < 4; q++) {
                int nt = 2*ks + (q >> 1);
                float x = s[nt][(q & 1) * 2];
                float y = s[nt][(q & 1) * 2 + 1];
                ah4[q] = pack_bf2(x, y);
                float2 hf = unpack_bf2(ah4[q]);
                al4[q] = pack_bf2(x - hf.x, y - hf.y);
            }
            #pragma unroll
            for (int dp = 0; dp < 4; dp++) {
                uint32_t vh4[4], vl4[4];
                LDSM4T(vh4, st + 18432 + (ks*16 + (lane & 15))*PB + dp*32 + (lane >> 4)*16);
                LDSM4T(vl4, st + 27648 + (ks*16 + (lane & 15))*PB + dp*32 + (lane >> 4)*16);
                MMA16816(o[2*dp],   ah4, vh4[0], vh4[1]);
                MMA16816(o[2*dp+1], ah4, vh4[2], vh4[3]);
                MMA16816(o[2*dp],   al4, vh4[0], vh4[1]);
                MMA16816(o[2*dp+1], al4, vh4[2], vh4[3]);
                MMA16816(o[2*dp],   ah4, vl4[0], vl4[1]);
                MMA16816(o[2*dp+1], ah4, vl4[2], vl4[3]);
            }
        }
        __syncthreads();
    }
    #undef LOADKV

    float inv0 = 1.0f / l0r, inv1 = 1.0f / l1r;
    __nv_bfloat16* oh = (__nv_bfloat16*)g_ah;
    __nv_bfloat16* ol = (__nv_bfloat16*)g_al;
    const size_t gr0 = (size_t)(rowbase + q0 + w*16 + row0) * DM + h*DH;
    const size_t gr1 = gr0 + 8 * DM;
    #pragma unroll
    for (int dt = 0; dt < 8; dt++) {
        int col = dt*8 + col2;
        float x0 = o[dt][0]*inv0, y0 = o[dt][1]*inv0;
        uint32_t h0 = pack_bf2(x0, y0);
        float2 f0 = unpack_bf2(h0);
        *(uint32_t*)&oh[gr0 + col] = h0;
        *(uint32_t*)&ol[gr0 + col] = pack_bf2(x0 - f0.x, y0 - f0.y);
        float x1 = o[dt][2]*inv1, y1 = o[dt][3]*inv1;
        uint32_t h1 = pack_bf2(x1, y1);
        float2 f1 = unpack_bf2(h1);
        *(uint32_t*)&oh[gr1 + col] = h1;
        *(uint32_t*)&ol[gr1 + col] = pack_bf2(x1 - f1.x, y1 - f1.y);
    }
}

// ---------------- launch -----------------------------------------------------
extern "C" void kernel_launch(void* const* d_in, const int* in_sizes, int n_in,
                              void* d_out, int out_size) {
    const float* hidden = (const float*)d_in[0];
    const float* Wq     = (const float*)d_in[1];
    const float* Wk     = (const float*)d_in[2];
    const float* Wv     = (const float*)d_in[3];
    const float* Wo     = (const float*)d_in[4];
    const float* relb   = (const float*)d_in[5];
    float* out = (float*)d_out;

    void *phh, *phl, *pxh, *pxl, *pah, *pal, *pwh, *pwl;
    cudaGetSymbolAddress(&phh, g_hh);
    cudaGetSymbolAddress(&phl, g_hl);
    cudaGetSymbolAddress(&pxh, g_xh);
    cudaGetSymbolAddress(&pxl, g_xl);
    cudaGetSymbolAddress(&pah, g_ah);
    cudaGetSymbolAddress(&pal, g_al);
    cudaGetSymbolAddress(&pwh, g_wh);
    cudaGetSymbolAddress(&pwl, g_wl);

    __nv_bfloat16* hh = (__nv_bfloat16*)phh;
    __nv_bfloat16* hl = (__nv_bfloat16*)phl;
    __nv_bfloat16* xh = (__nv_bfloat16*)pxh;
    __nv_bfloat16* xl = (__nv_bfloat16*)pxl;
    __nv_bfloat16* ah = (__nv_bfloat16*)pah;
    __nv_bfloat16* al = (__nv_bfloat16*)pal;
    __nv_bfloat16* wh = (__nv_bfloat16*)pwh;
    __nv_bfloat16* wl = (__nv_bfloat16*)pwl;

    int dev = 0, sms = GRID_SK;
    cudaGetDevice(&dev);
    cudaDeviceGetAttribute(&sms, cudaDevAttrMultiProcessorCount, dev);
    int grid_sk = (sms < GRID_SK) ? sms : GRID_SK;   // must be <= resident capacity

    convert_split<<<(MROWS*DM/4)/256, 256>>>(hidden, hh, hl);
    convert_w_all<<<dim3(DM/32, DM/32, 4), dim3(32, 8)>>>(Wq, Wk, Wv, Wo);
    bias_kernel<<<NH, 256>>>(relb);

    const int QKV_SMEM = 3 * ((2*128 + 2*256) * PITCHB);   // 184320
    const int WO_SMEM  = 3 * ((2*128 + 2*128) * PITCHB);   // 122880
    cudaFuncSetAttribute(gemm_sk<256,1>, cudaFuncAttributeMaxDynamicSharedMemorySize, QKV_SMEM);
    cudaFuncSetAttribute(gemm_sk<128,0>, cudaFuncAttributeMaxDynamicSharedMemorySize, WO_SMEM);

    // fused QKV: N=3072 (wq|wk|wv rows are contiguous in g_wh/g_wl)
    gemm_sk<256,1><<<grid_sk, 256, QKV_SMEM>>>(hh, hl, wh, wl,
        nullptr, xh, xl, /*NBLK=*/DM3/256, /*NT=*/(MROWS/128)*(DM3/256), /*ldc=*/DM3);

    cudaFuncSetAttribute(attn_mma, cudaFuncAttributeMaxDynamicSharedMemorySize, ATTN_SMEM);
    attn_mma<<<dim3(SEQ/BQ, BATCH*NH), 256, ATTN_SMEM>>>();

    // Wo: N=1024, fp32 out
    gemm_sk<128,0><<<grid_sk, 256, WO_SMEM>>>(ah, al, wh + 3*(size_t)DM*DM, wl + 3*(size_t)DM*DM,
        out, nullptr, nullptr, /*NBLK=*/DM/128, /*NT=*/(MROWS/128)*(DM/128), /*ldc=*/DM);
}